// round 12
// baseline (speedup 1.0000x reference)
#include <cuda_runtime.h>
#include <cuda_fp16.h>

#define N_NODES 100000
#define N_EDGES 3200000
#define FEAT 16
#define SCAN_TILE 1024
#define MAX_TILES 128

// Scratch in __device__ globals (no allocations allowed).
__device__ int   g_degi     [N_NODES];
__device__ int   g_rowstart [N_NODES + 1];
__device__ int   g_cursor   [N_NODES];
__device__ unsigned long long g_tile[MAX_TILES];   // lookback state
__device__ int   g_esrc     [N_EDGES];             // src ids, dst-sorted
__device__ float g_dinv     [N_NODES];
__device__ uint2 g_hsh1     [N_NODES * 4];         // fp16x2 messages, 32B/node
__device__ uint2 g_hsh2     [N_NODES * 4];

// ------------------------------------------------------------------ zero ----
__global__ void k_zero(int n) {
    int i = blockIdx.x * blockDim.x + threadIdx.x;
    if (i < n) g_degi[i] = 0;
    if (i < MAX_TILES) g_tile[i] = 0ULL;
}

// ------------------------------------------------------------------ hist ----
__global__ void k_hist(const int* __restrict__ dst, int E2) {
    int e = blockIdx.x * blockDim.x + threadIdx.x;
    if (e >= E2) return;
    int2 d = __ldg(((const int2*)dst) + e);
    atomicAdd(&g_degi[d.x], 1);
    atomicAdd(&g_degi[d.y], 1);
}

// --------------------------------------- single-pass scan (lookback) --------
// status in bits[33:32]: 1 = aggregate published, 2 = inclusive prefix.
__global__ void k_scan(int n, int E) {
    __shared__ int wsum[32];
    __shared__ int s_prefix;
    int t = threadIdx.x, bid = blockIdx.x;
    int idx = bid * SCAN_TILE + t;
    int v = (idx < n) ? g_degi[idx] : 0;
    int lane = t & 31, wid = t >> 5;

    int s = v;
#pragma unroll
    for (int off = 1; off < 32; off <<= 1) {
        int u = __shfl_up_sync(0xffffffffu, s, off);
        if (lane >= off) s += u;
    }
    if (lane == 31) wsum[wid] = s;
    __syncthreads();
    if (wid == 0) {
        int ws = wsum[lane];
#pragma unroll
        for (int off = 1; off < 32; off <<= 1) {
            int u = __shfl_up_sync(0xffffffffu, ws, off);
            if (lane >= off) ws += u;
        }
        wsum[lane] = ws;
    }
    __syncthreads();
    int incl  = s + ((wid > 0) ? wsum[wid - 1] : 0);
    int total = wsum[31];

    // publish + lookback (warp 0)
    if (wid == 0) {
        if (bid == 0) {
            if (lane == 0) {
                s_prefix = 0;
                atomicExch(&g_tile[0], (2ULL << 32) | (unsigned)total);
            }
        } else {
            if (lane == 0)
                atomicExch(&g_tile[bid], (1ULL << 32) | (unsigned)total);
            int ex = 0, base = bid - 1;
            bool done = false;
            while (!done) {
                int i = base - lane;
                unsigned long long stw = (i >= 0) ? atomicAdd(&g_tile[i], 0ULL)
                                                  : (1ULL << 32);   // AGG,0
                unsigned stat = (unsigned)(stw >> 32);
                int val = (int)(unsigned)stw;
                unsigned pre_mask  = __ballot_sync(0xffffffffu, stat == 2u);
                unsigned none_mask = __ballot_sync(0xffffffffu, stat == 0u);
                if (pre_mask) {
                    int lp = __ffs(pre_mask) - 1;          // closest PREFIX
                    if ((none_mask & ((1u << lp) - 1)) == 0) {
                        int c = (lane <= lp) ? val : 0;
#pragma unroll
                        for (int off = 16; off; off >>= 1)
                            c += __shfl_down_sync(0xffffffffu, c, off);
                        ex += __shfl_sync(0xffffffffu, c, 0);
                        done = true;
                    }
                } else if (none_mask == 0) {               // window all AGG
                    int c = val;
#pragma unroll
                    for (int off = 16; off; off >>= 1)
                        c += __shfl_down_sync(0xffffffffu, c, off);
                    ex += __shfl_sync(0xffffffffu, c, 0);
                    base -= 32;                            // block0 is PRE, so
                }                                          // base never < 0 here
            }
            if (lane == 0) {
                s_prefix = ex;
                atomicExch(&g_tile[bid], (2ULL << 32) | (unsigned)(ex + total));
            }
        }
    }
    __syncthreads();
    int ex = s_prefix;
    if (idx < n) {
        int r = ex + incl - v;   // global exclusive
        g_rowstart[idx] = r;
        g_cursor[idx]   = r;
    }
    if (idx == 0) g_rowstart[n] = E;
}

// ----------------------------------------------------------------- bucket ---
__global__ void k_bucket(const int* __restrict__ src,
                         const int* __restrict__ dst, int E2) {
    int e = blockIdx.x * blockDim.x + threadIdx.x;
    if (e >= E2) return;
    int2 s2 = __ldg(((const int2*)src) + e);
    int2 d2 = __ldg(((const int2*)dst) + e);
    int p0 = atomicAdd(&g_cursor[d2.x], 1);
    g_esrc[p0] = s2.x;
    int p1 = atomicAdd(&g_cursor[d2.y], 1);
    g_esrc[p1] = s2.y;
}

// ---------------------------------------------------------- layer 1 xform ----
__global__ void k_transform1(const float* __restrict__ x,
                             const float* __restrict__ W, int n) {
    __shared__ float sW[16][16];
    int t = threadIdx.x;
    if (t < 256) sW[t >> 4][t & 15] = W[t];
    __syncthreads();

    int i = blockIdx.x * blockDim.x + t;
    if (i >= n) return;

    float di = rsqrtf((float)g_degi[i] + 1.0f);   // +1 self loop
    g_dinv[i] = di;

    const float4* xr = (const float4*)(x + (size_t)i * FEAT);
    float xin[16];
#pragma unroll
    for (int q = 0; q < 4; q++) {
        float4 v = xr[q];
        xin[4*q+0] = v.x; xin[4*q+1] = v.y; xin[4*q+2] = v.z; xin[4*q+3] = v.w;
    }

    uint2* hp = &g_hsh1[(size_t)i * 4];
#pragma unroll
    for (int qq = 0; qq < 4; qq++) {
        float o[4];
#pragma unroll
        for (int jj = 0; jj < 4; jj++) {
            int j = 4*qq + jj;
            float s = 0.0f;
#pragma unroll
            for (int k = 0; k < 16; k++) s = fmaf(xin[k], sW[k][j], s);
            o[jj] = s * di;
        }
        __half2 p0 = __floats2half2_rn(o[0], o[1]);
        __half2 p1 = __floats2half2_rn(o[2], o[3]);
        hp[qq] = make_uint2(*(unsigned*)&p0, *(unsigned*)&p1);
    }
}

// --------------------------------------------- agg1 + transform2 (fused) ----
// Warp per node: gather+reduce layer-1 messages, then lanes 0-3 apply the
// layer-1 epilogue (relu(*di + b1)), do the 16x16 matvec against W2 in-warp
// via shfl broadcast, scale by di, and store the fp16 layer-2 messages.
__global__ void k_agg1t2(const float* __restrict__ W2,
                         const float* __restrict__ b1, int n) {
    __shared__ float sW[16][16];
    __shared__ float sb[16];
    int t = threadIdx.x;
    if (t < 256) sW[t >> 4][t & 15] = W2[t];
    if (t < 16) sb[t] = b1[t];
    __syncthreads();

    int gw   = (blockIdx.x * blockDim.x + t) >> 5;
    int lane = t & 31;
    if (gw >= n) return;
    int q    = lane & 3;
    int slot = lane >> 2;

    int beg = g_rowstart[gw];
    int end = g_rowstart[gw + 1];

    float4 acc = make_float4(0.f, 0.f, 0.f, 0.f);
#pragma unroll 2
    for (int j = beg + slot; j < end; j += 8) {
        int s = __ldg(&g_esrc[j]);
        uint2 w = __ldg(&g_hsh1[(size_t)s * 4 + q]);
        float2 f0 = __half22float2(*(__half2*)&w.x);
        float2 f1 = __half22float2(*(__half2*)&w.y);
        acc.x += f0.x; acc.y += f0.y; acc.z += f1.x; acc.w += f1.y;
    }
#pragma unroll
    for (int off = 16; off >= 4; off >>= 1) {
        acc.x += __shfl_down_sync(0xffffffffu, acc.x, off);
        acc.y += __shfl_down_sync(0xffffffffu, acc.y, off);
        acc.z += __shfl_down_sync(0xffffffffu, acc.z, off);
        acc.w += __shfl_down_sync(0xffffffffu, acc.w, off);
    }
    if (lane < 4) {
        uint2 sw = __ldg(&g_hsh1[(size_t)gw * 4 + lane]);   // self loop
        float2 s0 = __half22float2(*(__half2*)&sw.x);
        float2 s1 = __half22float2(*(__half2*)&sw.y);
        float di = g_dinv[gw];
        float hloc[4];
        hloc[0] = fmaxf(fmaf(acc.x + s0.x, di, sb[lane*4+0]), 0.0f);
        hloc[1] = fmaxf(fmaf(acc.y + s0.y, di, sb[lane*4+1]), 0.0f);
        hloc[2] = fmaxf(fmaf(acc.z + s1.x, di, sb[lane*4+2]), 0.0f);
        hloc[3] = fmaxf(fmaf(acc.w + s1.y, di, sb[lane*4+3]), 0.0f);

        float o[4];
#pragma unroll
        for (int jj = 0; jj < 4; jj++) {
            int j = lane * 4 + jj;
            float s = 0.0f;
#pragma unroll
            for (int k = 0; k < 16; k++) {
                float hk = __shfl_sync(0x0000000Fu, hloc[k & 3], k >> 2, 4);
                s = fmaf(hk, sW[k][j], s);
            }
            o[jj] = s * di;
        }
        __half2 p0 = __floats2half2_rn(o[0], o[1]);
        __half2 p1 = __floats2half2_rn(o[2], o[3]);
        g_hsh2[(size_t)gw * 4 + lane] = make_uint2(*(unsigned*)&p0,
                                                   *(unsigned*)&p1);
    }
}

// --------------------------------------------- agg2 + output epilogue -------
__global__ void k_agg2(const float* __restrict__ b2,
                       float* __restrict__ out, int n) {
    int gw   = (blockIdx.x * blockDim.x + threadIdx.x) >> 5;
    int lane = threadIdx.x & 31;
    if (gw >= n) return;
    int q    = lane & 3;
    int slot = lane >> 2;

    int beg = g_rowstart[gw];
    int end = g_rowstart[gw + 1];

    float4 acc = make_float4(0.f, 0.f, 0.f, 0.f);
#pragma unroll 2
    for (int j = beg + slot; j < end; j += 8) {
        int s = __ldg(&g_esrc[j]);
        uint2 w = __ldg(&g_hsh2[(size_t)s * 4 + q]);
        float2 f0 = __half22float2(*(__half2*)&w.x);
        float2 f1 = __half22float2(*(__half2*)&w.y);
        acc.x += f0.x; acc.y += f0.y; acc.z += f1.x; acc.w += f1.y;
    }
#pragma unroll
    for (int off = 16; off >= 4; off >>= 1) {
        acc.x += __shfl_down_sync(0xffffffffu, acc.x, off);
        acc.y += __shfl_down_sync(0xffffffffu, acc.y, off);
        acc.z += __shfl_down_sync(0xffffffffu, acc.z, off);
        acc.w += __shfl_down_sync(0xffffffffu, acc.w, off);
    }
    if (lane < 4) {
        uint2 sw = __ldg(&g_hsh2[(size_t)gw * 4 + lane]);   // self loop
        float2 s0 = __half22float2(*(__half2*)&sw.x);
        float2 s1 = __half22float2(*(__half2*)&sw.y);
        float di = g_dinv[gw];
        float4 bb = __ldg(((const float4*)b2) + lane);
        float4 o;
        o.x = fmaf(acc.x + s0.x, di, bb.x);
        o.y = fmaf(acc.y + s0.y, di, bb.y);
        o.z = fmaf(acc.z + s1.x, di, bb.z);
        o.w = fmaf(acc.w + s1.y, di, bb.w);
        ((float4*)out)[(size_t)gw * 4 + lane] = o;
    }
}

// ---------------------------------------------------------------- launch ----
extern "C" void kernel_launch(void* const* d_in, const int* in_sizes, int n_in,
                              void* d_out, int out_size) {
    const float* x    = (const float*)d_in[0];
    const int*   eidx = (const int*)  d_in[1];
    const float* W1   = (const float*)d_in[2];
    const float* b1   = (const float*)d_in[3];
    const float* W2   = (const float*)d_in[4];
    const float* b2   = (const float*)d_in[5];
    float* out = (float*)d_out;

    int n = in_sizes[0] / FEAT;       // 100000
    int E = in_sizes[1] / 2;          // 3200000
    const int* src = eidx;
    const int* dst = eidx + E;

    const int B = 256;
    int gn  = (n + B - 1) / B;                    // node-parallel grid
    int E2  = E / 2;                              // int2-vectorized edges
    int ge2 = (E2 + B - 1) / B;
    int nt  = (n + SCAN_TILE - 1) / SCAN_TILE;    // scan tiles (98)
    int gw  = (n * 32 + B - 1) / B;               // warp-per-node grid

    // CSR build (shared by both layers)
    k_zero  <<<gn, B>>>(n);
    k_hist  <<<ge2, B>>>(dst, E2);
    k_scan  <<<nt, SCAN_TILE>>>(n, E);
    k_bucket<<<ge2, B>>>(src, dst, E2);

    // Layers (transform2 fused into agg1, output epilogue fused into agg2)
    k_transform1<<<gn, B>>>(x, W1, n);
    k_agg1t2    <<<gw, B>>>(W2, b1, n);
    k_agg2      <<<gw, B>>>(b2, out, n);
}

// round 13
// speedup vs baseline: 1.0400x; 1.0400x over previous
#include <cuda_runtime.h>
#include <cuda_fp16.h>

#define N_NODES 100000
#define N_EDGES 3200000
#define FEAT 16
#define SCAN_TILE 1024
#define MAX_TILES 128

// Scratch in __device__ globals (no allocations allowed).
__device__ int   g_degi     [N_NODES];
__device__ int   g_rowstart [N_NODES + 1];
__device__ unsigned long long g_tile[MAX_TILES];   // lookback state
__device__ unsigned short g_rank[N_EDGES];         // edge rank within dst bucket
__device__ int   g_esrc     [N_EDGES];             // src ids, dst-sorted
__device__ float g_dinv     [N_NODES];
__device__ uint2 g_hsh1     [N_NODES * 4];         // fp16x2 messages, 32B/node
__device__ uint2 g_hsh2     [N_NODES * 4];

// ------------------------------------------------------------------ zero ----
__global__ void k_zero(int n) {
    int i = blockIdx.x * blockDim.x + threadIdx.x;
    if (i < n) g_degi[i] = 0;
    if (i < MAX_TILES) g_tile[i] = 0ULL;
}

// ------------------------------------------------------------------ hist ----
// Histogram AND per-edge rank (the atomic's return value) in one pass.
__global__ void k_hist(const int* __restrict__ dst, int E) {
    int e = blockIdx.x * blockDim.x + threadIdx.x;
    if (e >= E) return;
    int d = __ldg(dst + e);
    int r = atomicAdd(&g_degi[d], 1);
    g_rank[e] = (unsigned short)r;
}

// --------------------------------------- single-pass scan (lookback) --------
// status in bits[33:32]: 1 = aggregate published, 2 = inclusive prefix.
__global__ void k_scan(int n, int E) {
    __shared__ int wsum[32];
    __shared__ int s_prefix;
    int t = threadIdx.x, bid = blockIdx.x;
    int idx = bid * SCAN_TILE + t;
    int v = (idx < n) ? g_degi[idx] : 0;
    int lane = t & 31, wid = t >> 5;

    int s = v;
#pragma unroll
    for (int off = 1; off < 32; off <<= 1) {
        int u = __shfl_up_sync(0xffffffffu, s, off);
        if (lane >= off) s += u;
    }
    if (lane == 31) wsum[wid] = s;
    __syncthreads();
    if (wid == 0) {
        int ws = wsum[lane];
#pragma unroll
        for (int off = 1; off < 32; off <<= 1) {
            int u = __shfl_up_sync(0xffffffffu, ws, off);
            if (lane >= off) ws += u;
        }
        wsum[lane] = ws;
    }
    __syncthreads();
    int incl  = s + ((wid > 0) ? wsum[wid - 1] : 0);
    int total = wsum[31];

    // publish + lookback (warp 0)
    if (wid == 0) {
        if (bid == 0) {
            if (lane == 0) {
                s_prefix = 0;
                atomicExch(&g_tile[0], (2ULL << 32) | (unsigned)total);
            }
        } else {
            if (lane == 0)
                atomicExch(&g_tile[bid], (1ULL << 32) | (unsigned)total);
            int ex = 0, base = bid - 1;
            bool done = false;
            while (!done) {
                int i = base - lane;
                unsigned long long stw = (i >= 0) ? atomicAdd(&g_tile[i], 0ULL)
                                                  : (1ULL << 32);   // AGG,0
                unsigned stat = (unsigned)(stw >> 32);
                int val = (int)(unsigned)stw;
                unsigned pre_mask  = __ballot_sync(0xffffffffu, stat == 2u);
                unsigned none_mask = __ballot_sync(0xffffffffu, stat == 0u);
                if (pre_mask) {
                    int lp = __ffs(pre_mask) - 1;          // closest PREFIX
                    if ((none_mask & ((1u << lp) - 1)) == 0) {
                        int c = (lane <= lp) ? val : 0;
#pragma unroll
                        for (int off = 16; off; off >>= 1)
                            c += __shfl_down_sync(0xffffffffu, c, off);
                        ex += __shfl_sync(0xffffffffu, c, 0);
                        done = true;
                    }
                } else if (none_mask == 0) {               // window all AGG
                    int c = val;
#pragma unroll
                    for (int off = 16; off; off >>= 1)
                        c += __shfl_down_sync(0xffffffffu, c, off);
                    ex += __shfl_sync(0xffffffffu, c, 0);
                    base -= 32;                            // block0 is PRE, so
                }                                          // base never < 0 here
            }
            if (lane == 0) {
                s_prefix = ex;
                atomicExch(&g_tile[bid], (2ULL << 32) | (unsigned)(ex + total));
            }
        }
    }
    __syncthreads();
    int ex = s_prefix;
    if (idx < n)
        g_rowstart[idx] = ex + incl - v;   // global exclusive
    if (idx == 0) g_rowstart[n] = E;
}

// ----------------------------------------------------------------- bucket ---
// Atomic-free placement: pos = rowstart[dst] + rank (saved during hist).
__global__ void k_bucket(const int* __restrict__ src,
                         const int* __restrict__ dst, int E) {
    int e = blockIdx.x * blockDim.x + threadIdx.x;
    if (e >= E) return;
    int d = __ldg(dst + e);
    int pos = __ldg(&g_rowstart[d]) + (int)g_rank[e];
    g_esrc[pos] = __ldg(src + e);
}

// ---------------------------------------------------------- layer 1 xform ----
__global__ void k_transform1(const float* __restrict__ x,
                             const float* __restrict__ W, int n) {
    __shared__ float sW[16][16];
    int t = threadIdx.x;
    if (t < 256) sW[t >> 4][t & 15] = W[t];
    __syncthreads();

    int i = blockIdx.x * blockDim.x + t;
    if (i >= n) return;

    float di = rsqrtf((float)g_degi[i] + 1.0f);   // +1 self loop
    g_dinv[i] = di;

    const float4* xr = (const float4*)(x + (size_t)i * FEAT);
    float xin[16];
#pragma unroll
    for (int q = 0; q < 4; q++) {
        float4 v = xr[q];
        xin[4*q+0] = v.x; xin[4*q+1] = v.y; xin[4*q+2] = v.z; xin[4*q+3] = v.w;
    }

    uint2* hp = &g_hsh1[(size_t)i * 4];
#pragma unroll
    for (int qq = 0; qq < 4; qq++) {
        float o[4];
#pragma unroll
        for (int jj = 0; jj < 4; jj++) {
            int j = 4*qq + jj;
            float s = 0.0f;
#pragma unroll
            for (int k = 0; k < 16; k++) s = fmaf(xin[k], sW[k][j], s);
            o[jj] = s * di;
        }
        __half2 p0 = __floats2half2_rn(o[0], o[1]);
        __half2 p1 = __floats2half2_rn(o[2], o[3]);
        hp[qq] = make_uint2(*(unsigned*)&p0, *(unsigned*)&p1);
    }
}

// --------------------------------------------- agg1 + transform2 (fused) ----
// Warp per node: gather+reduce layer-1 messages, then lanes 0-3 apply the
// layer-1 epilogue (relu(*di + b1)), do the 16x16 matvec against W2 in-warp
// via shfl broadcast, scale by di, and store the fp16 layer-2 messages.
__global__ void k_agg1t2(const float* __restrict__ W2,
                         const float* __restrict__ b1, int n) {
    __shared__ float sW[16][16];
    __shared__ float sb[16];
    int t = threadIdx.x;
    if (t < 256) sW[t >> 4][t & 15] = W2[t];
    if (t < 16) sb[t] = b1[t];
    __syncthreads();

    int gw   = (blockIdx.x * blockDim.x + t) >> 5;
    int lane = t & 31;
    if (gw >= n) return;
    int q    = lane & 3;
    int slot = lane >> 2;

    int beg = g_rowstart[gw];
    int end = g_rowstart[gw + 1];

    float4 acc = make_float4(0.f, 0.f, 0.f, 0.f);
#pragma unroll 2
    for (int j = beg + slot; j < end; j += 8) {
        int s = __ldg(&g_esrc[j]);
        uint2 w = __ldg(&g_hsh1[(size_t)s * 4 + q]);
        float2 f0 = __half22float2(*(__half2*)&w.x);
        float2 f1 = __half22float2(*(__half2*)&w.y);
        acc.x += f0.x; acc.y += f0.y; acc.z += f1.x; acc.w += f1.y;
    }
#pragma unroll
    for (int off = 16; off >= 4; off >>= 1) {
        acc.x += __shfl_down_sync(0xffffffffu, acc.x, off);
        acc.y += __shfl_down_sync(0xffffffffu, acc.y, off);
        acc.z += __shfl_down_sync(0xffffffffu, acc.z, off);
        acc.w += __shfl_down_sync(0xffffffffu, acc.w, off);
    }
    if (lane < 4) {
        uint2 sw = __ldg(&g_hsh1[(size_t)gw * 4 + lane]);   // self loop
        float2 s0 = __half22float2(*(__half2*)&sw.x);
        float2 s1 = __half22float2(*(__half2*)&sw.y);
        float di = g_dinv[gw];
        float hloc[4];
        hloc[0] = fmaxf(fmaf(acc.x + s0.x, di, sb[lane*4+0]), 0.0f);
        hloc[1] = fmaxf(fmaf(acc.y + s0.y, di, sb[lane*4+1]), 0.0f);
        hloc[2] = fmaxf(fmaf(acc.z + s1.x, di, sb[lane*4+2]), 0.0f);
        hloc[3] = fmaxf(fmaf(acc.w + s1.y, di, sb[lane*4+3]), 0.0f);

        float o[4];
#pragma unroll
        for (int jj = 0; jj < 4; jj++) {
            int j = lane * 4 + jj;
            float s = 0.0f;
#pragma unroll
            for (int k = 0; k < 16; k++) {
                float hk = __shfl_sync(0x0000000Fu, hloc[k & 3], k >> 2, 4);
                s = fmaf(hk, sW[k][j], s);
            }
            o[jj] = s * di;
        }
        __half2 p0 = __floats2half2_rn(o[0], o[1]);
        __half2 p1 = __floats2half2_rn(o[2], o[3]);
        g_hsh2[(size_t)gw * 4 + lane] = make_uint2(*(unsigned*)&p0,
                                                   *(unsigned*)&p1);
    }
}

// --------------------------------------------- agg2 + output epilogue -------
__global__ void k_agg2(const float* __restrict__ b2,
                       float* __restrict__ out, int n) {
    int gw   = (blockIdx.x * blockDim.x + threadIdx.x) >> 5;
    int lane = threadIdx.x & 31;
    if (gw >= n) return;
    int q    = lane & 3;
    int slot = lane >> 2;

    int beg = g_rowstart[gw];
    int end = g_rowstart[gw + 1];

    float4 acc = make_float4(0.f, 0.f, 0.f, 0.f);
#pragma unroll 2
    for (int j = beg + slot; j < end; j += 8) {
        int s = __ldg(&g_esrc[j]);
        uint2 w = __ldg(&g_hsh2[(size_t)s * 4 + q]);
        float2 f0 = __half22float2(*(__half2*)&w.x);
        float2 f1 = __half22float2(*(__half2*)&w.y);
        acc.x += f0.x; acc.y += f0.y; acc.z += f1.x; acc.w += f1.y;
    }
#pragma unroll
    for (int off = 16; off >= 4; off >>= 1) {
        acc.x += __shfl_down_sync(0xffffffffu, acc.x, off);
        acc.y += __shfl_down_sync(0xffffffffu, acc.y, off);
        acc.z += __shfl_down_sync(0xffffffffu, acc.z, off);
        acc.w += __shfl_down_sync(0xffffffffu, acc.w, off);
    }
    if (lane < 4) {
        uint2 sw = __ldg(&g_hsh2[(size_t)gw * 4 + lane]);   // self loop
        float2 s0 = __half22float2(*(__half2*)&sw.x);
        float2 s1 = __half22float2(*(__half2*)&sw.y);
        float di = g_dinv[gw];
        float4 bb = __ldg(((const float4*)b2) + lane);
        float4 o;
        o.x = fmaf(acc.x + s0.x, di, bb.x);
        o.y = fmaf(acc.y + s0.y, di, bb.y);
        o.z = fmaf(acc.z + s1.x, di, bb.z);
        o.w = fmaf(acc.w + s1.y, di, bb.w);
        ((float4*)out)[(size_t)gw * 4 + lane] = o;
    }
}

// ---------------------------------------------------------------- launch ----
extern "C" void kernel_launch(void* const* d_in, const int* in_sizes, int n_in,
                              void* d_out, int out_size) {
    const float* x    = (const float*)d_in[0];
    const int*   eidx = (const int*)  d_in[1];
    const float* W1   = (const float*)d_in[2];
    const float* b1   = (const float*)d_in[3];
    const float* W2   = (const float*)d_in[4];
    const float* b2   = (const float*)d_in[5];
    float* out = (float*)d_out;

    int n = in_sizes[0] / FEAT;       // 100000
    int E = in_sizes[1] / 2;          // 3200000
    const int* src = eidx;
    const int* dst = eidx + E;

    const int B = 256;
    int gn = (n + B - 1) / B;                    // node-parallel grid
    int ge = (E + B - 1) / B;                    // edge-parallel grid
    int nt = (n + SCAN_TILE - 1) / SCAN_TILE;    // scan tiles (98)
    int gw = (n * 32 + B - 1) / B;               // warp-per-node grid

    // CSR build (shared by both layers)
    k_zero  <<<gn, B>>>(n);
    k_hist  <<<ge, B>>>(dst, E);
    k_scan  <<<nt, SCAN_TILE>>>(n, E);
    k_bucket<<<ge, B>>>(src, dst, E);

    // Layers (transform2 fused into agg1, output epilogue fused into agg2)
    k_transform1<<<gn, B>>>(x, W1, n);
    k_agg1t2    <<<gw, B>>>(W2, b1, n);
    k_agg2      <<<gw, B>>>(b2, out, n);
}

// round 14
// speedup vs baseline: 1.1918x; 1.1459x over previous
#include <cuda_runtime.h>
#include <cuda_fp16.h>

#define N_NODES 100000
#define N_EDGES 3200000
#define FEAT 16
#define SCAN_TILE 1024
#define MAX_TILES 128

// Scratch in __device__ globals (no allocations allowed).
__device__ int   g_degi     [N_NODES];
__device__ int   g_rowstart [N_NODES + 1];
__device__ unsigned long long g_tile[MAX_TILES];   // lookback state
__device__ unsigned short g_rank[N_EDGES];         // edge rank within dst bucket
__device__ int   g_esrc     [N_EDGES];             // src ids, dst-sorted
__device__ float g_dinv     [N_NODES];
__device__ uint2 g_hsh1     [N_NODES * 4];         // fp16x2 messages, 32B/node
__device__ uint2 g_hsh2     [N_NODES * 4];
__device__ float4 g_agg1    [N_NODES * 4];         // layer-1 aggregate (fp32)

// ------------------------------------------------------------------ zero ----
__global__ void k_zero(int n) {
    int i = blockIdx.x * blockDim.x + threadIdx.x;
    if (i < n) g_degi[i] = 0;
    if (i < MAX_TILES) g_tile[i] = 0ULL;
}

// ------------------------------------------------------------------ hist ----
// Histogram AND per-edge rank (the atomic's return value) in one pass.
__global__ void k_hist(const int* __restrict__ dst, int E) {
    int e = blockIdx.x * blockDim.x + threadIdx.x;
    if (e >= E) return;
    int d = __ldg(dst + e);
    int r = atomicAdd(&g_degi[d], 1);
    g_rank[e] = (unsigned short)r;
}

// --------------------------------------- single-pass scan (lookback) --------
// status in bits[33:32]: 1 = aggregate published, 2 = inclusive prefix.
__global__ void k_scan(int n, int E) {
    __shared__ int wsum[32];
    __shared__ int s_prefix;
    int t = threadIdx.x, bid = blockIdx.x;
    int idx = bid * SCAN_TILE + t;
    int v = (idx < n) ? g_degi[idx] : 0;
    int lane = t & 31, wid = t >> 5;

    int s = v;
#pragma unroll
    for (int off = 1; off < 32; off <<= 1) {
        int u = __shfl_up_sync(0xffffffffu, s, off);
        if (lane >= off) s += u;
    }
    if (lane == 31) wsum[wid] = s;
    __syncthreads();
    if (wid == 0) {
        int ws = wsum[lane];
#pragma unroll
        for (int off = 1; off < 32; off <<= 1) {
            int u = __shfl_up_sync(0xffffffffu, ws, off);
            if (lane >= off) ws += u;
        }
        wsum[lane] = ws;
    }
    __syncthreads();
    int incl  = s + ((wid > 0) ? wsum[wid - 1] : 0);
    int total = wsum[31];

    // publish + lookback (warp 0)
    if (wid == 0) {
        if (bid == 0) {
            if (lane == 0) {
                s_prefix = 0;
                atomicExch(&g_tile[0], (2ULL << 32) | (unsigned)total);
            }
        } else {
            if (lane == 0)
                atomicExch(&g_tile[bid], (1ULL << 32) | (unsigned)total);
            int ex = 0, base = bid - 1;
            bool done = false;
            while (!done) {
                int i = base - lane;
                unsigned long long stw = (i >= 0) ? atomicAdd(&g_tile[i], 0ULL)
                                                  : (1ULL << 32);   // AGG,0
                unsigned stat = (unsigned)(stw >> 32);
                int val = (int)(unsigned)stw;
                unsigned pre_mask  = __ballot_sync(0xffffffffu, stat == 2u);
                unsigned none_mask = __ballot_sync(0xffffffffu, stat == 0u);
                if (pre_mask) {
                    int lp = __ffs(pre_mask) - 1;          // closest PREFIX
                    if ((none_mask & ((1u << lp) - 1)) == 0) {
                        int c = (lane <= lp) ? val : 0;
#pragma unroll
                        for (int off = 16; off; off >>= 1)
                            c += __shfl_down_sync(0xffffffffu, c, off);
                        ex += __shfl_sync(0xffffffffu, c, 0);
                        done = true;
                    }
                } else if (none_mask == 0) {               // window all AGG
                    int c = val;
#pragma unroll
                    for (int off = 16; off; off >>= 1)
                        c += __shfl_down_sync(0xffffffffu, c, off);
                    ex += __shfl_sync(0xffffffffu, c, 0);
                    base -= 32;                            // block0 is PRE, so
                }                                          // base never < 0 here
            }
            if (lane == 0) {
                s_prefix = ex;
                atomicExch(&g_tile[bid], (2ULL << 32) | (unsigned)(ex + total));
            }
        }
    }
    __syncthreads();
    int ex = s_prefix;
    if (idx < n)
        g_rowstart[idx] = ex + incl - v;   // global exclusive
    if (idx == 0) g_rowstart[n] = E;
}

// ----------------------------------------------------------------- bucket ---
// Atomic-free placement: pos = rowstart[dst] + rank (saved during hist).
__global__ void k_bucket(const int* __restrict__ src,
                         const int* __restrict__ dst, int E) {
    int e = blockIdx.x * blockDim.x + threadIdx.x;
    if (e >= E) return;
    int d = __ldg(dst + e);
    int pos = __ldg(&g_rowstart[d]) + (int)g_rank[e];
    g_esrc[pos] = __ldg(src + e);
}

// ---------------------------------------------------------- layer 1 xform ----
__global__ void k_transform1(const float* __restrict__ x,
                             const float* __restrict__ W, int n) {
    __shared__ float sW[16][16];
    int t = threadIdx.x;
    if (t < 256) sW[t >> 4][t & 15] = W[t];
    __syncthreads();

    int i = blockIdx.x * blockDim.x + t;
    if (i >= n) return;

    float di = rsqrtf((float)g_degi[i] + 1.0f);   // +1 self loop
    g_dinv[i] = di;

    const float4* xr = (const float4*)(x + (size_t)i * FEAT);
    float xin[16];
#pragma unroll
    for (int q = 0; q < 4; q++) {
        float4 v = xr[q];
        xin[4*q+0] = v.x; xin[4*q+1] = v.y; xin[4*q+2] = v.z; xin[4*q+3] = v.w;
    }

    uint2* hp = &g_hsh1[(size_t)i * 4];
#pragma unroll
    for (int qq = 0; qq < 4; qq++) {
        float o[4];
#pragma unroll
        for (int jj = 0; jj < 4; jj++) {
            int j = 4*qq + jj;
            float s = 0.0f;
#pragma unroll
            for (int k = 0; k < 16; k++) s = fmaf(xin[k], sW[k][j], s);
            o[jj] = s * di;
        }
        __half2 p0 = __floats2half2_rn(o[0], o[1]);
        __half2 p1 = __floats2half2_rn(o[2], o[3]);
        hp[qq] = make_uint2(*(unsigned*)&p0, *(unsigned*)&p1);
    }
}

// ------------------------------------------------------------- aggregate ----
// One warp per node; lanes = 8 edge-slots x 4 feature-quarters.
// fp16 gather (32B/edge = 1 sector), fp32 register accumulation, shfl
// reduction, one plain store per node. Zero atomics.
template <int LAYER>
__global__ void k_agg(const float* __restrict__ b2,
                      float* __restrict__ out, int n) {
    int gw   = (blockIdx.x * blockDim.x + threadIdx.x) >> 5;
    int lane = threadIdx.x & 31;
    if (gw >= n) return;
    int q    = lane & 3;
    int slot = lane >> 2;

    int beg = g_rowstart[gw];
    int end = g_rowstart[gw + 1];
    const uint2* hs = (LAYER == 1) ? g_hsh1 : g_hsh2;

    float4 acc = make_float4(0.f, 0.f, 0.f, 0.f);
#pragma unroll 2
    for (int j = beg + slot; j < end; j += 8) {
        int s = __ldg(&g_esrc[j]);
        uint2 w = __ldg(&hs[(size_t)s * 4 + q]);
        float2 f0 = __half22float2(*(__half2*)&w.x);
        float2 f1 = __half22float2(*(__half2*)&w.y);
        acc.x += f0.x; acc.y += f0.y; acc.z += f1.x; acc.w += f1.y;
    }
#pragma unroll
    for (int off = 16; off >= 4; off >>= 1) {
        acc.x += __shfl_down_sync(0xffffffffu, acc.x, off);
        acc.y += __shfl_down_sync(0xffffffffu, acc.y, off);
        acc.z += __shfl_down_sync(0xffffffffu, acc.z, off);
        acc.w += __shfl_down_sync(0xffffffffu, acc.w, off);
    }
    if (lane < 4) {
        uint2 sw = __ldg(&hs[(size_t)gw * 4 + lane]);    // self loop
        float2 s0 = __half22float2(*(__half2*)&sw.x);
        float2 s1 = __half22float2(*(__half2*)&sw.y);
        acc.x += s0.x; acc.y += s0.y; acc.z += s1.x; acc.w += s1.y;
        if (LAYER == 1) {
            g_agg1[(size_t)gw * 4 + lane] = acc;
        } else {
            float di = g_dinv[gw];
            float4 bb = __ldg(((const float4*)b2) + lane);
            acc.x = fmaf(acc.x, di, bb.x);
            acc.y = fmaf(acc.y, di, bb.y);
            acc.z = fmaf(acc.z, di, bb.z);
            acc.w = fmaf(acc.w, di, bb.w);
            ((float4*)out)[(size_t)gw * 4 + lane] = acc;
        }
    }
}

// ------------------------------------------- layer1 epilogue + layer2 xform -
__global__ void k_transform2(const float* __restrict__ W2,
                             const float* __restrict__ b1, int n) {
    __shared__ float sW[16][16];
    __shared__ float sb[16];
    int t = threadIdx.x;
    if (t < 256) sW[t >> 4][t & 15] = W2[t];
    if (t < 16) sb[t] = b1[t];
    __syncthreads();

    int i = blockIdx.x * blockDim.x + t;
    if (i >= n) return;

    float di = g_dinv[i];
    const float4* ap1 = &g_agg1[(size_t)i * 4];
    float hin[16];
#pragma unroll
    for (int q = 0; q < 4; q++) {
        float4 v = ap1[q];
        hin[4*q+0] = v.x; hin[4*q+1] = v.y; hin[4*q+2] = v.z; hin[4*q+3] = v.w;
    }
#pragma unroll
    for (int k = 0; k < 16; k++)
        hin[k] = fmaxf(fmaf(hin[k], di, sb[k]), 0.0f);   // *dinv + b1, relu

    uint2* hp = &g_hsh2[(size_t)i * 4];
#pragma unroll
    for (int qq = 0; qq < 4; qq++) {
        float o[4];
#pragma unroll
        for (int jj = 0; jj < 4; jj++) {
            int j = 4*qq + jj;
            float s = 0.0f;
#pragma unroll
            for (int k = 0; k < 16; k++) s = fmaf(hin[k], sW[k][j], s);
            o[jj] = s * di;
        }
        __half2 p0 = __floats2half2_rn(o[0], o[1]);
        __half2 p1 = __floats2half2_rn(o[2], o[3]);
        hp[qq] = make_uint2(*(unsigned*)&p0, *(unsigned*)&p1);
    }
}

// ---------------------------------------------------------------- launch ----
extern "C" void kernel_launch(void* const* d_in, const int* in_sizes, int n_in,
                              void* d_out, int out_size) {
    const float* x    = (const float*)d_in[0];
    const int*   eidx = (const int*)  d_in[1];
    const float* W1   = (const float*)d_in[2];
    const float* b1   = (const float*)d_in[3];
    const float* W2   = (const float*)d_in[4];
    const float* b2   = (const float*)d_in[5];
    float* out = (float*)d_out;

    int n = in_sizes[0] / FEAT;       // 100000
    int E = in_sizes[1] / 2;          // 3200000
    const int* src = eidx;
    const int* dst = eidx + E;

    const int B = 256;
    int gn = (n + B - 1) / B;                    // node-parallel grid
    int ge = (E + B - 1) / B;                    // edge-parallel grid
    int nt = (n + SCAN_TILE - 1) / SCAN_TILE;    // scan tiles (98)
    int gw = (n * 32 + B - 1) / B;               // warp-per-node grid

    // CSR build (shared by both layers)
    k_zero  <<<gn, B>>>(n);
    k_hist  <<<ge, B>>>(dst, E);
    k_scan  <<<nt, SCAN_TILE>>>(n, E);
    k_bucket<<<ge, B>>>(src, dst, E);

    // Layer 1
    k_transform1<<<gn, B>>>(x, W1, n);
    k_agg<1>    <<<gw, B>>>(nullptr, nullptr, n);
    // Layer 2 (output epilogue fused into agg2)
    k_transform2<<<gn, B>>>(W2, b1, n);
    k_agg<2>    <<<gw, B>>>(b2, out, n);
}